// round 4
// baseline (speedup 1.0000x reference)
#include <cuda_runtime.h>
#include <math.h>

#define B_SAMPLES 16384
#define EMB 64

__device__ int g_p_off[B_SAMPLES + 1];
__device__ int g_w_off[B_SAMPLES + 1];

__device__ __forceinline__ int lower_bound_i(const int* __restrict__ a, int n, int v) {
    int lo = 0, hi = n;
    while (lo < hi) {
        int m = (lo + hi) >> 1;
        if (__ldg(a + m) < v) lo = m + 1; else hi = m;
    }
    return lo;
}

__global__ void __launch_bounds__(256) offsets_kernel(
    const int* __restrict__ p_seg, int TP,
    const int* __restrict__ w_seg, int TW)
{
    int t = blockIdx.x * blockDim.x + threadIdx.x;
    if (t > B_SAMPLES) return;
    g_p_off[t] = lower_bound_i(p_seg, TP, t);
    g_w_off[t] = lower_bound_i(w_seg, TW, t);
}

// Half-warp-per-row gather: lanes 0-15 take even rows, 16-31 odd rows.
// Each lane loads float4 (16B); one warp load instruction covers 2 rows (512B).
// Result: acc = per-half partial sum of this lane's 4 dims.
__device__ __forceinline__ float4 segment_accum_h(
    const int* __restrict__ idx, int s, int n,
    const float4* __restrict__ table4, int h, int sub)
{
    float4 a0 = {0.f,0.f,0.f,0.f}, a1 = {0.f,0.f,0.f,0.f};
    float4 a2 = {0.f,0.f,0.f,0.f}, a3 = {0.f,0.f,0.f,0.f};

    const int cnt = (n - h + 1) >> 1;   // rows this half owns
    const int* base = idx + s + h;

    int k = 0;
    for (; k + 4 <= cnt; k += 4) {
        int r0 = __ldg(base + 2*(k+0));
        int r1 = __ldg(base + 2*(k+1));
        int r2 = __ldg(base + 2*(k+2));
        int r3 = __ldg(base + 2*(k+3));
        float4 v0 = __ldg(table4 + (size_t)r0 * 16 + sub);
        float4 v1 = __ldg(table4 + (size_t)r1 * 16 + sub);
        float4 v2 = __ldg(table4 + (size_t)r2 * 16 + sub);
        float4 v3 = __ldg(table4 + (size_t)r3 * 16 + sub);
        a0.x += v0.x; a0.y += v0.y; a0.z += v0.z; a0.w += v0.w;
        a1.x += v1.x; a1.y += v1.y; a1.z += v1.z; a1.w += v1.w;
        a2.x += v2.x; a2.y += v2.y; a2.z += v2.z; a2.w += v2.w;
        a3.x += v3.x; a3.y += v3.y; a3.z += v3.z; a3.w += v3.w;
    }
    for (; k < cnt; k++) {
        int r = __ldg(base + 2*k);
        float4 v = __ldg(table4 + (size_t)r * 16 + sub);
        a0.x += v.x; a0.y += v.y; a0.z += v.z; a0.w += v.w;
    }
    float4 out;
    out.x = (a0.x + a1.x) + (a2.x + a3.x);
    out.y = (a0.y + a1.y) + (a2.y + a3.y);
    out.z = (a0.z + a1.z) + (a2.z + a3.z);
    out.w = (a0.w + a1.w) + (a2.w + a3.w);
    return out;
}

__global__ void __launch_bounds__(128) svdpp_kernel(
    const int* __restrict__ sci_ids,
    const int* __restrict__ pap_ids,
    const int* __restrict__ p_idx,
    const int* __restrict__ w_idx,
    const float* __restrict__ s_fact,
    const float* __restrict__ p_fact,
    const float* __restrict__ s_bias,
    const float* __restrict__ p_bias,
    const float* __restrict__ imp_fact,
    const float* __restrict__ imp_wish,
    const float* __restrict__ g_bias,
    float* __restrict__ out)
{
    const int warp_id = (blockIdx.x * blockDim.x + threadIdx.x) >> 5;
    if (warp_id >= B_SAMPLES) return;
    const int b = warp_id;
    const int lane = threadIdx.x & 31;
    const int h = lane >> 4;      // which half-warp (row parity)
    const int sub = lane & 15;    // 4 dims starting at sub*4

    const int ps = g_p_off[b];
    const int pn = g_p_off[b + 1] - ps;
    const int ws = g_w_off[b];
    const int wn = g_w_off[b + 1] - ws;

    const int sid = sci_ids[b];
    const int pid = pap_ids[b];
    float4 se = __ldg(reinterpret_cast<const float4*>(s_fact) + (size_t)sid * 16 + sub);
    float4 pv = __ldg(reinterpret_cast<const float4*>(p_fact) + (size_t)pid * 16 + sub);

    float4 yp = segment_accum_h(p_idx, ps, pn,
                                reinterpret_cast<const float4*>(imp_fact), h, sub);
    float4 yw = segment_accum_h(w_idx, ws, wn,
                                reinterpret_cast<const float4*>(imp_wish), h, sub);

    const float pscale = rsqrtf(fmaxf((float)pn, 1.0f));
    const float wscale = rsqrtf(fmaxf((float)wn, 1.0f));

    // Combine scaled pools into one float4, then merge the two halves.
    float4 y;
    y.x = yp.x * pscale + yw.x * wscale;
    y.y = yp.y * pscale + yw.y * wscale;
    y.z = yp.z * pscale + yw.z * wscale;
    y.w = yp.w * pscale + yw.w * wscale;
    y.x += __shfl_xor_sync(0xFFFFFFFFu, y.x, 16);
    y.y += __shfl_xor_sync(0xFFFFFFFFu, y.y, 16);
    y.z += __shfl_xor_sync(0xFFFFFFFFu, y.z, 16);
    y.w += __shfl_xor_sync(0xFFFFFFFFu, y.w, 16);

    // Dot product over this lane's 4 dims (lanes 16-31 duplicate 0-15).
    float d = (se.x + y.x) * pv.x + (se.y + y.y) * pv.y
            + (se.z + y.z) * pv.z + (se.w + y.w) * pv.w;

    // Reduce over the 16 distinct sublanes.
    d += __shfl_xor_sync(0xFFFFFFFFu, d, 8);
    d += __shfl_xor_sync(0xFFFFFFFFu, d, 4);
    d += __shfl_xor_sync(0xFFFFFFFFu, d, 2);
    d += __shfl_xor_sync(0xFFFFFFFFu, d, 1);

    if (lane == 0) {
        out[b] = d + __ldg(s_bias + sid) + __ldg(p_bias + pid) + __ldg(g_bias);
    }
}

extern "C" void kernel_launch(void* const* d_in, const int* in_sizes, int n_in,
                              void* d_out, int out_size)
{
    const int*   sci_ids = (const int*)d_in[0];
    const int*   pap_ids = (const int*)d_in[1];
    const int*   p_idx   = (const int*)d_in[2];
    const int*   p_seg   = (const int*)d_in[3];
    const int*   w_idx   = (const int*)d_in[4];
    const int*   w_seg   = (const int*)d_in[5];
    const float* s_fact  = (const float*)d_in[6];
    const float* p_fact  = (const float*)d_in[7];
    const float* s_bias  = (const float*)d_in[8];
    const float* p_bias  = (const float*)d_in[9];
    const float* imp_f   = (const float*)d_in[10];
    const float* imp_w   = (const float*)d_in[11];
    const float* g_bias  = (const float*)d_in[12];
    float* out = (float*)d_out;

    const int TP = in_sizes[2];
    const int TW = in_sizes[4];

    offsets_kernel<<<(B_SAMPLES + 1 + 255) / 256, 256>>>(p_seg, TP, w_seg, TW);

    const int threads = 128;                  // 4 warps per block
    const int blocks = B_SAMPLES / (threads / 32);
    svdpp_kernel<<<blocks, threads>>>(
        sci_ids, pap_ids, p_idx, w_idx,
        s_fact, p_fact, s_bias, p_bias, imp_f, imp_w, g_bias, out);
}

// round 5
// speedup vs baseline: 1.2231x; 1.2231x over previous
#include <cuda_runtime.h>
#include <math.h>

#define B_SAMPLES 16384
#define EMB 64

__device__ int g_p_off[B_SAMPLES + 1];
__device__ int g_w_off[B_SAMPLES + 1];

// Boundary-scan offsets: for sorted seg, off[v] = lower_bound(seg, v).
// Thread i writes off[v] = i for all v in (seg[i-1], seg[i]].
__device__ __forceinline__ void scan_one(const int* __restrict__ seg, int T,
                                         int* __restrict__ off, int i)
{
    int cur = __ldg(seg + i);
    int prev = (i == 0) ? -1 : __ldg(seg + i - 1);
    for (int v = prev + 1; v <= cur; v++) off[v] = i;
    if (i == T - 1) {
        for (int v = cur + 1; v <= B_SAMPLES; v++) off[v] = T;
    }
}

__global__ void __launch_bounds__(256) offsets_kernel(
    const int* __restrict__ p_seg, int TP,
    const int* __restrict__ w_seg, int TW)
{
    int t = blockIdx.x * blockDim.x + threadIdx.x;
    if (t < TP) {
        scan_one(p_seg, TP, g_p_off, t);
    } else if (t < TP + TW) {
        scan_one(w_seg, TW, g_w_off, t - TP);
    }
}

// Warp gather with shfl-broadcast indices: one coalesced idx load per 32 rows,
// then 32 independent 256B row loads (float2 per lane).
__device__ __forceinline__ void gather_shfl(
    const int* __restrict__ idx, int s, int e,
    const float2* __restrict__ t2, int lane,
    float& ax, float& ay)
{
    float a0x=0.f,a0y=0.f,a1x=0.f,a1y=0.f,a2x=0.f,a2y=0.f,a3x=0.f,a3y=0.f;

    int i = s;
    while (i + 32 <= e) {
        int c = __ldg(idx + i + lane);
        #pragma unroll
        for (int k = 0; k < 32; k += 4) {
            int r0 = __shfl_sync(0xFFFFFFFFu, c, k + 0);
            int r1 = __shfl_sync(0xFFFFFFFFu, c, k + 1);
            int r2 = __shfl_sync(0xFFFFFFFFu, c, k + 2);
            int r3 = __shfl_sync(0xFFFFFFFFu, c, k + 3);
            float2 v0 = __ldg(t2 + (size_t)r0 * 32 + lane);
            float2 v1 = __ldg(t2 + (size_t)r1 * 32 + lane);
            float2 v2 = __ldg(t2 + (size_t)r2 * 32 + lane);
            float2 v3 = __ldg(t2 + (size_t)r3 * 32 + lane);
            a0x += v0.x; a0y += v0.y;
            a1x += v1.x; a1y += v1.y;
            a2x += v2.x; a2y += v2.y;
            a3x += v3.x; a3y += v3.y;
        }
        i += 32;
    }

    const int rem = e - i;
    if (rem > 0) {
        int pos = i + (lane < rem ? lane : rem - 1);   // clamp: stay in-bounds
        int c = __ldg(idx + pos);
        int k = 0;
        for (; k + 4 <= rem; k += 4) {
            int r0 = __shfl_sync(0xFFFFFFFFu, c, k + 0);
            int r1 = __shfl_sync(0xFFFFFFFFu, c, k + 1);
            int r2 = __shfl_sync(0xFFFFFFFFu, c, k + 2);
            int r3 = __shfl_sync(0xFFFFFFFFu, c, k + 3);
            float2 v0 = __ldg(t2 + (size_t)r0 * 32 + lane);
            float2 v1 = __ldg(t2 + (size_t)r1 * 32 + lane);
            float2 v2 = __ldg(t2 + (size_t)r2 * 32 + lane);
            float2 v3 = __ldg(t2 + (size_t)r3 * 32 + lane);
            a0x += v0.x; a0y += v0.y;
            a1x += v1.x; a1y += v1.y;
            a2x += v2.x; a2y += v2.y;
            a3x += v3.x; a3y += v3.y;
        }
        for (; k < rem; k++) {
            int r = __shfl_sync(0xFFFFFFFFu, c, k);
            float2 v = __ldg(t2 + (size_t)r * 32 + lane);
            a0x += v.x; a0y += v.y;
        }
    }

    ax += (a0x + a1x) + (a2x + a3x);
    ay += (a0y + a1y) + (a2y + a3y);
}

__global__ void __launch_bounds__(256) svdpp_kernel(
    const int* __restrict__ sci_ids,
    const int* __restrict__ pap_ids,
    const int* __restrict__ p_idx,
    const int* __restrict__ w_idx,
    const float* __restrict__ s_fact,
    const float* __restrict__ p_fact,
    const float* __restrict__ s_bias,
    const float* __restrict__ p_bias,
    const float* __restrict__ imp_fact,
    const float* __restrict__ imp_wish,
    const float* __restrict__ g_bias,
    float* __restrict__ out)
{
    const int warp_id = (blockIdx.x * blockDim.x + threadIdx.x) >> 5;
    if (warp_id >= B_SAMPLES) return;
    const int b = warp_id;
    const int lane = threadIdx.x & 31;

    const int ps = g_p_off[b];
    const int pe = g_p_off[b + 1];
    const int ws = g_w_off[b];
    const int we = g_w_off[b + 1];

    const int sid = __ldg(sci_ids + b);
    const int pid = __ldg(pap_ids + b);
    float2 se = __ldg(reinterpret_cast<const float2*>(s_fact) + (size_t)sid * 32 + lane);
    float2 pv = __ldg(reinterpret_cast<const float2*>(p_fact) + (size_t)pid * 32 + lane);

    float px = 0.f, py = 0.f;
    gather_shfl(p_idx, ps, pe,
                reinterpret_cast<const float2*>(imp_fact), lane, px, py);
    const float pscale = rsqrtf(fmaxf((float)(pe - ps), 1.0f));

    float wx = 0.f, wy = 0.f;
    gather_shfl(w_idx, ws, we,
                reinterpret_cast<const float2*>(imp_wish), lane, wx, wy);
    const float wscale = rsqrtf(fmaxf((float)(we - ws), 1.0f));

    const float yx = px * pscale + wx * wscale;
    const float yy = py * pscale + wy * wscale;

    float d = (se.x + yx) * pv.x + (se.y + yy) * pv.y;

    #pragma unroll
    for (int off = 16; off > 0; off >>= 1)
        d += __shfl_xor_sync(0xFFFFFFFFu, d, off);

    if (lane == 0) {
        out[b] = d + __ldg(s_bias + sid) + __ldg(p_bias + pid) + __ldg(g_bias);
    }
}

extern "C" void kernel_launch(void* const* d_in, const int* in_sizes, int n_in,
                              void* d_out, int out_size)
{
    const int*   sci_ids = (const int*)d_in[0];
    const int*   pap_ids = (const int*)d_in[1];
    const int*   p_idx   = (const int*)d_in[2];
    const int*   p_seg   = (const int*)d_in[3];
    const int*   w_idx   = (const int*)d_in[4];
    const int*   w_seg   = (const int*)d_in[5];
    const float* s_fact  = (const float*)d_in[6];
    const float* p_fact  = (const float*)d_in[7];
    const float* s_bias  = (const float*)d_in[8];
    const float* p_bias  = (const float*)d_in[9];
    const float* imp_f   = (const float*)d_in[10];
    const float* imp_w   = (const float*)d_in[11];
    const float* g_bias  = (const float*)d_in[12];
    float* out = (float*)d_out;

    const int TP = in_sizes[2];
    const int TW = in_sizes[4];

    // Pass 1: boundary-scan segment offsets (one thread per idx element).
    const int total = TP + TW;
    offsets_kernel<<<(total + 255) / 256, 256>>>(p_seg, TP, w_seg, TW);

    // Pass 2: one warp per sample.
    const int threads = 256;
    const int blocks = B_SAMPLES / (threads / 32);
    svdpp_kernel<<<blocks, threads>>>(
        sci_ids, pap_ids, p_idx, w_idx,
        s_fact, p_fact, s_bias, p_bias, imp_f, imp_w, g_bias, out);
}